// round 16
// baseline (speedup 1.0000x reference)
#include <cuda_runtime.h>
#include <cuda_fp16.h>
#include <cstdint>

#define NB    2048
#define N2    4096
#define DDIM  1024
#define INV_T 14.285714285714286f

#define BM 128
#define BN 128
#define NCHUNK 16                            // K chunks of 64 fp16 (128B rows)
#define NSTAGE 2
#define BLK_BYTES 16384                      // 128 rows x 64 fp16, swizzled
#define STAGE_BYTES (2 * BLK_BYTES)          // A + B = 32KB
#define DYN_SMEM (NSTAGE * STAGE_BYTES)      // 64KB -> 2 CTAs/SM (512 thr)
#define ROW_TILES 32
#define NTILES_UT 528
#define NOFFDIAG 496
#define NTHREADS 512
#define GRID_MAIN 296                        // exactly 2 CTAs/SM: co-resident

// ---------------- device globals -------------------------------------------
__device__ __align__(1024) unsigned char g_zb[NCHUNK * ROW_TILES * BLK_BYTES]; // 8MB fp16
__device__ float g_denom[N2];
__device__ float g_pos[N2];
__device__ int   g_tilectr;
__device__ int   g_done;
__device__ int   g_norm_done;

// ---------------- asm helpers ----------------------------------------------
__device__ __forceinline__ uint32_t smem_u32(const void* p) {
    uint32_t a;
    asm("{ .reg .u64 t; cvta.to.shared.u64 t, %1; cvt.u32.u64 %0, t; }"
        : "=r"(a) : "l"(p));
    return a;
}

#define MBAR_INIT(addr, cnt) \
    asm volatile("mbarrier.init.shared.b64 [%0], %1;" :: "r"(addr), "r"(cnt) : "memory")
#define MBAR_EXPECT_TX(addr, bytes) \
    asm volatile("mbarrier.arrive.expect_tx.shared.b64 _, [%0], %1;" :: "r"(addr), "r"(bytes) : "memory")

#define MBAR_WAIT(addr, parity) do {                                          \
    uint32_t _m = (addr), _p = (uint32_t)(parity), _d;                        \
    asm volatile("{\n\t.reg .pred p;\n\t"                                     \
        "mbarrier.try_wait.parity.acquire.cta.shared::cta.b64 p, [%1], %2;\n\t" \
        "selp.b32 %0, 1, 0, p;\n\t}"                                          \
        : "=r"(_d) : "r"(_m), "r"(_p) : "memory");                            \
    if (!_d) {                                                                \
        asm volatile("{\n\t.reg .pred P1;\n\t"                                \
            "W_%=:\n\t"                                                       \
            "mbarrier.try_wait.parity.acquire.cta.shared::cta.b64 P1, [%0], %1, 0x989680;\n\t" \
            "@P1 bra.uni D_%=;\n\t"                                           \
            "bra.uni W_%=;\n\t"                                               \
            "D_%=:\n\t}" :: "r"(_m), "r"(_p) : "memory");                     \
    }                                                                         \
} while (0)

__device__ __forceinline__ void bulk_g2s(uint32_t dst, const void* src,
                                         uint32_t bytes, uint32_t mbar) {
    asm volatile(
        "cp.async.bulk.shared::cta.global.mbarrier::complete_tx::bytes [%0], [%1], %2, [%3];"
        :: "r"(dst), "l"(src), "r"(bytes), "r"(mbar) : "memory");
}

#define LDSM_X4(r, addr)                                                      \
    asm volatile("ldmatrix.sync.aligned.m8n8.x4.shared.b16 {%0,%1,%2,%3}, [%4];" \
        : "=r"((r)[0]), "=r"((r)[1]), "=r"((r)[2]), "=r"((r)[3]) : "r"(addr))

#define MMA16816H(d, a, b0, b1)                                               \
    asm volatile("mma.sync.aligned.m16n8k16.row.col.f16.f16.f16.f16 "         \
        "{%0,%1}, {%2,%3,%4,%5}, {%6,%7}, {%0,%1};"                           \
        : "+r"((d)[0]), "+r"((d)[1])                                          \
        : "r"((a)[0]), "r"((a)[1]), "r"((a)[2]), "r"((a)[3]),                 \
          "r"(b0), "r"(b1))

// ---------------------------------------------------------------------------
// Single persistent kernel:
//   Phase 1: L2-normalize + fp16 quantize into swizzled tile blocks; zero
//            accumulators; reset tile/done counters.
//   Global software barrier (all 296 CTAs co-resident by construction).
//   Phase 2: work-stealing upper-tri fp16 GEMM (R15 mainloop) + symmetric
//            exp epilogue.
//   Phase 3: last CTA computes mean loss; resets barrier counter.
// ---------------------------------------------------------------------------
__global__ void __launch_bounds__(NTHREADS, 2) supcon_kernel(
    const float* __restrict__ feat, float* __restrict__ out)
{
    extern __shared__ __align__(1024) unsigned char dynsmem[];
    __shared__ __align__(8) unsigned long long mb_full[NSTAGE];
    __shared__ int s_tile;
    __shared__ int s_last;
    const uint32_t smem_base = smem_u32(dynsmem);
    const uint32_t full0     = smem_u32(&mb_full[0]);

    const int tid    = threadIdx.x;
    const int lane   = tid & 31;
    const int warp   = tid >> 5;       // 0..15
    const int bid    = blockIdx.x;

    // ======================= Phase 1: normalize ==============================
    {
        const int r = bid * 16 + warp;          // one warp per row, 4736 >= 4096
        if (r < N2) {
            const int b = r & (NB - 1);
            const int v = r >> 11;
            const float4* __restrict__ src =
                reinterpret_cast<const float4*>(feat + ((size_t)b * 2 + v) * DDIM);
            float4 x[8];
            float ss = 0.f;
            #pragma unroll
            for (int j = 0; j < 8; ++j) {
                x[j] = __ldcs(src + j * 32 + lane);
                ss += x[j].x * x[j].x + x[j].y * x[j].y + x[j].z * x[j].z + x[j].w * x[j].w;
            }
            #pragma unroll
            for (int o = 16; o; o >>= 1) ss += __shfl_xor_sync(0xffffffffu, ss, o);
            const float inv = 1.0f / fmaxf(sqrtf(ss), 1e-12f);

            const int rt = r >> 7;
            const int m  = r & 127;
            #pragma unroll
            for (int j = 0; j < 8; ++j) {
                const int k  = j * 128 + lane * 4;
                const int kc = k >> 6;
                const int c  = k & 63;
                __half2 h01 = __floats2half2_rn(x[j].x * inv, x[j].y * inv);
                __half2 h23 = __floats2half2_rn(x[j].z * inv, x[j].w * inv);
                uint2 val;
                val.x = *reinterpret_cast<uint32_t*>(&h01);
                val.y = *reinterpret_cast<uint32_t*>(&h23);
                uint32_t off = (uint32_t)(m * 128 + c * 2);
                uint32_t sw  = off ^ ((off >> 3) & 0x70);
                *reinterpret_cast<uint2*>(
                    g_zb + (size_t)(kc * ROW_TILES + rt) * BLK_BYTES + sw) = val;
            }
        }
        const int gid = bid * NTHREADS + tid;
        if (gid < N2) { g_denom[gid] = 0.0f; g_pos[gid] = 0.0f; }
        if (gid == 0) { g_tilectr = 0; g_done = 0; }
    }

    // mbarrier init (local, before barrier)
    if (tid == 0) {
        #pragma unroll
        for (int s = 0; s < NSTAGE; ++s) MBAR_INIT(full0 + 8 * s, 1);
    }

    // ================== global software barrier ==============================
    __threadfence();
    __syncthreads();
    if (tid == 0) {
        atomicAdd(&g_norm_done, 1);
        while (atomicAdd(&g_norm_done, 0) < GRID_MAIN) __nanosleep(128);
    }
    __syncthreads();
    __threadfence();

    // ======================= Phase 2: GEMM tiles =============================
    const int warp_m = warp & 3;       // 4 warps along M (32 rows each)
    const int warp_n = warp >> 2;      // 4 warps along N (32 cols each)

    const uint32_t lrow = (uint32_t)(lane & 15);
    const uint32_t hi16 = (uint32_t)((lane >> 4) * 16);
    const uint32_t swz  = (lrow & 7) << 4;
    const uint32_t aRowOff = (uint32_t)((warp_m * 32 + lrow) * 128);

    for (;;) {
        __syncthreads();
        if (tid == 0) s_tile = atomicAdd(&g_tilectr, 1);
        __syncthreads();
        const int t = s_tile;
        if (t >= NTILES_UT) break;

        // Tile map: idx < 496 -> off-diag (bi<bj); idx >= 496 -> diag.
        int bi, bj;
        if (t < NOFFDIAG) {
            int rem = t; bi = 0;
            while (rem >= 31 - bi) { rem -= 31 - bi; ++bi; }
            bj = bi + 1 + rem;
        } else {
            bi = bj = t - NOFFDIAG;
        }
        const bool diag = (bi == bj);
        const int row0 = bi * BM;
        const int col0 = bj * BN;

        auto issue_chunk = [&](int stage, int kc) {
            if (tid == 0) {
                const uint32_t bar = full0 + 8 * stage;
                const uint32_t sA  = smem_base + stage * STAGE_BYTES;
                const unsigned char* gA = g_zb + (size_t)(kc * ROW_TILES + bi) * BLK_BYTES;
                MBAR_EXPECT_TX(bar, diag ? BLK_BYTES : 2 * BLK_BYTES);
                bulk_g2s(sA, gA, BLK_BYTES, bar);
                if (!diag) {
                    const unsigned char* gB = g_zb + (size_t)(kc * ROW_TILES + bj) * BLK_BYTES;
                    bulk_g2s(sA + BLK_BYTES, gB, BLK_BYTES, bar);
                }
            }
        };

        uint32_t acc[2][2][2][2];
        #pragma unroll
        for (int mi = 0; mi < 2; ++mi)
            #pragma unroll
            for (int ni = 0; ni < 2; ++ni)
                #pragma unroll
                for (int h = 0; h < 2; ++h) { acc[mi][ni][h][0] = 0u; acc[mi][ni][h][1] = 0u; }

        issue_chunk(0, 0);

        const uint32_t bRowOff = (uint32_t)((diag ? 0 : BLK_BYTES) +
                                            (warp_n * 32 + lrow) * 128);

        for (int kc = 0; kc < NCHUNK; ++kc) {
            const int stage = kc & 1;
            MBAR_WAIT(full0 + 8 * stage, (kc >> 1) & 1);
            __syncthreads();
            if (kc + 1 < NCHUNK) issue_chunk((kc + 1) & 1, kc + 1);

            const uint32_t sBase = smem_base + stage * STAGE_BYTES;
            const uint32_t aBase = sBase + aRowOff;
            const uint32_t bBase = sBase + bRowOff;

            #pragma unroll
            for (int ks = 0; ks < 4; ++ks) {
                const uint32_t off = (uint32_t)((ks * 32 + hi16)) ^ swz;
                uint32_t a[2][4], b[2][4];
                LDSM_X4(a[0], aBase + off);
                LDSM_X4(a[1], aBase + 16 * 128 + off);
                LDSM_X4(b[0], bBase + off);
                LDSM_X4(b[1], bBase + 16 * 128 + off);

                #pragma unroll
                for (int mi = 0; mi < 2; ++mi)
                    #pragma unroll
                    for (int ni = 0; ni < 2; ++ni) {
                        MMA16816H(acc[mi][ni][0], a[mi], b[ni][0], b[ni][2]);
                        MMA16816H(acc[mi][ni][1], a[mi], b[ni][1], b[ni][3]);
                    }
            }
        }
        // 16 chunks / 2 stages = 8 waits per stage -> mbar parity returns to 0.

        // ---- fused symmetric epilogue --------------------------------------
        float csum[2][2][2];
        #pragma unroll
        for (int ni = 0; ni < 2; ++ni)
            #pragma unroll
            for (int h = 0; h < 2; ++h) { csum[ni][h][0] = 0.f; csum[ni][h][1] = 0.f; }

        #pragma unroll
        for (int mi = 0; mi < 2; ++mi) {
            float rsum0 = 0.f, rsum1 = 0.f;
            const int mbase = row0 + warp_m * 32 + mi * 16 + (lane >> 2);
            #pragma unroll
            for (int ni = 0; ni < 2; ++ni)
                #pragma unroll
                for (int h = 0; h < 2; ++h) {
                    const int nbase = col0 + warp_n * 32 + ni * 16 + h * 8 + (lane & 3) * 2;
                    #pragma unroll
                    for (int rr = 0; rr < 2; ++rr) {
                        const float2 f = __half22float2(
                            *reinterpret_cast<const __half2*>(&acc[mi][ni][h][rr]));
                        const int m = mbase + rr * 8;
                        #pragma unroll
                        for (int p = 0; p < 2; ++p) {
                            const int n = nbase + p;
                            const float v = p ? f.y : f.x;
                            if (!diag && n == (m ^ 2048)) { g_pos[m] = v; g_pos[n] = v; }
                            const float ev = (diag && n == m) ? 0.f : __expf(v * INV_T);
                            if (rr) rsum1 += ev; else rsum0 += ev;
                            if (!diag) csum[ni][h][p] += ev;
                        }
                    }
                }
            rsum0 += __shfl_down_sync(0xffffffffu, rsum0, 2);
            rsum0 += __shfl_down_sync(0xffffffffu, rsum0, 1);
            rsum1 += __shfl_down_sync(0xffffffffu, rsum1, 2);
            rsum1 += __shfl_down_sync(0xffffffffu, rsum1, 1);
            if ((lane & 3) == 0) {
                atomicAdd(&g_denom[mbase], rsum0);
                atomicAdd(&g_denom[mbase + 8], rsum1);
            }
        }

        if (!diag) {
            #pragma unroll
            for (int ni = 0; ni < 2; ++ni)
                #pragma unroll
                for (int h = 0; h < 2; ++h)
                    #pragma unroll
                    for (int p = 0; p < 2; ++p) {
                        float c = csum[ni][h][p];
                        c += __shfl_xor_sync(0xffffffffu, c, 4);
                        c += __shfl_xor_sync(0xffffffffu, c, 8);
                        c += __shfl_xor_sync(0xffffffffu, c, 16);
                        if (lane < 4)
                            atomicAdd(&g_denom[col0 + warp_n * 32 + ni * 16 + h * 8 +
                                               lane * 2 + p], c);
                    }
        }
    }

    // ================== Phase 3: fused finalize ==============================
    __threadfence();
    __syncthreads();
    if (tid == 0) {
        const int old = atomicAdd(&g_done, 1);
        s_last = (old == GRID_MAIN - 1);
    }
    __syncthreads();
    if (s_last) {
        __threadfence();
        float accl = 0.f;
        for (int r = tid; r < N2; r += NTHREADS)
            accl += -(g_pos[r] * INV_T - logf(g_denom[r]));
        #pragma unroll
        for (int o = 16; o; o >>= 1) accl += __shfl_xor_sync(0xffffffffu, accl, o);
        __shared__ float ws[16];
        if ((tid & 31) == 0) ws[tid >> 5] = accl;
        __syncthreads();
        if (tid == 0) {
            float tot = 0.f;
            #pragma unroll
            for (int i = 0; i < 16; ++i) tot += ws[i];
            out[0] = tot / (float)N2;
            g_norm_done = 0;            // reset barrier for next graph replay
        }
    }
}

// ---------------------------------------------------------------------------
extern "C" void kernel_launch(void* const* d_in, const int* in_sizes, int n_in,
                              void* d_out, int out_size)
{
    const float* feat = (const float*)d_in[0];
    float* out = (float*)d_out;

    cudaFuncSetAttribute(supcon_kernel,
                         cudaFuncAttributeMaxDynamicSharedMemorySize, DYN_SMEM);

    supcon_kernel<<<GRID_MAIN, NTHREADS, DYN_SMEM>>>(feat, out);
}